// round 2
// baseline (speedup 1.0000x reference)
#include <cuda_runtime.h>
#include <cuda_bf16.h>
#include <math.h>

// ---------------- problem constants ----------------
#define B_  4
#define T_  2048
#define C_  1024
#define H_  8
#define DH_ 128
#define DFF_ 4096
#define M_  (B_ * T_)            // 8192 rows

// ---------------- scratch (device globals, no allocation) ----------------
__device__ float g_h1[M_ * C_];                       // LN1 output
__device__ float g_q [B_ * H_ * T_ * DH_];
__device__ float g_k [B_ * H_ * T_ * DH_];
__device__ float g_v [B_ * H_ * T_ * DH_];
__device__ float g_sc[(size_t)B_ * H_ * T_ * T_];     // 512 MB scores / probs
__device__ float g_x1[M_ * C_];                       // x + attn_out
__device__ float g_h2[M_ * C_];                       // LN2 output
__device__ float g_f1[M_ * DFF_];                     // relu(h2 w1 + b1)

// ---------------- shared GEMM core: 128x128 tile, 8x8/thread, Ktile=8 ----------------
#define BSTR 132   // padded smem row stride (conflict-free scatter stores)

template<bool TB>
__device__ __forceinline__ void gemm_core(const float* __restrict__ A, int lda,
                                          const float* __restrict__ B, int ldb,
                                          int K, float acc[8][8])
{
    __shared__ float As[8 * BSTR];
    __shared__ float Bs[8 * BSTR];
    const int tid = threadIdx.x;
    const int tx  = tid & 15;
    const int ty  = tid >> 4;
    const int lm  = tid >> 1;          // 0..127  (row of A tile / row of B^T tile)
    const int lk4 = (tid & 1) * 4;     // 0 or 4
    const int bk  = tid >> 5;          // 0..7    (NN B loader)
    const int bn4 = (tid & 31) * 4;

    for (int kt = 0; kt < K; kt += 8) {
        // ---- load A tile (rows lm, cols kt..kt+7), transpose into As[k][m]
        float4 av = *(const float4*)(A + (size_t)lm * lda + kt + lk4);
        As[(lk4 + 0) * BSTR + lm] = av.x;
        As[(lk4 + 1) * BSTR + lm] = av.y;
        As[(lk4 + 2) * BSTR + lm] = av.z;
        As[(lk4 + 3) * BSTR + lm] = av.w;
        if (TB) {
            // B is [N,K] row-major; Bs[k][n] = B[n][k]
            float4 bv = *(const float4*)(B + (size_t)lm * ldb + kt + lk4);
            Bs[(lk4 + 0) * BSTR + lm] = bv.x;
            Bs[(lk4 + 1) * BSTR + lm] = bv.y;
            Bs[(lk4 + 2) * BSTR + lm] = bv.z;
            Bs[(lk4 + 3) * BSTR + lm] = bv.w;
        } else {
            // B is [K,N] row-major
            float4 bv = *(const float4*)(B + (size_t)(kt + bk) * ldb + bn4);
            *(float4*)(&Bs[bk * BSTR + bn4]) = bv;
        }
        __syncthreads();

        #pragma unroll
        for (int kk = 0; kk < 8; kk++) {
            float a[8], b[8];
            *(float4*)(a)     = *(const float4*)(&As[kk * BSTR + ty * 8]);
            *(float4*)(a + 4) = *(const float4*)(&As[kk * BSTR + ty * 8 + 4]);
            *(float4*)(b)     = *(const float4*)(&Bs[kk * BSTR + tx * 8]);
            *(float4*)(b + 4) = *(const float4*)(&Bs[kk * BSTR + tx * 8 + 4]);
            #pragma unroll
            for (int i = 0; i < 8; i++)
                #pragma unroll
                for (int j = 0; j < 8; j++)
                    acc[i][j] += a[i] * b[j];
        }
        __syncthreads();
    }
}

// ---------------- LayerNorm ----------------
__device__ __forceinline__ void block_reduce2(float& a, float& b)
{
    #pragma unroll
    for (int o = 16; o; o >>= 1) {
        a += __shfl_xor_sync(0xFFFFFFFFu, a, o);
        b += __shfl_xor_sync(0xFFFFFFFFu, b, o);
    }
    __shared__ float sa[8], sb[8];
    int w = threadIdx.x >> 5, l = threadIdx.x & 31;
    if (l == 0) { sa[w] = a; sb[w] = b; }
    __syncthreads();
    a = 0.f; b = 0.f;
    #pragma unroll
    for (int i = 0; i < 8; i++) { a += sa[i]; b += sb[i]; }
}

__global__ void ln_kernel(const float* __restrict__ x, const float* __restrict__ g,
                          const float* __restrict__ bb, float* __restrict__ out)
{
    size_t row = blockIdx.x;
    const float4* xr = (const float4*)(x + row * C_);
    float4 v = xr[threadIdx.x];
    float s  = v.x + v.y + v.z + v.w;
    float sq = v.x * v.x + v.y * v.y + v.z * v.z + v.w * v.w;
    block_reduce2(s, sq);
    float mean = s * (1.0f / C_);
    float var  = sq * (1.0f / C_) - mean * mean;
    float inv  = rsqrtf(var + 1e-5f);
    float4 gv = ((const float4*)g)[threadIdx.x];
    float4 bv = ((const float4*)bb)[threadIdx.x];
    float4 o;
    o.x = (v.x - mean) * inv * gv.x + bv.x;
    o.y = (v.y - mean) * inv * gv.y + bv.y;
    o.z = (v.z - mean) * inv * gv.z + bv.z;
    o.w = (v.w - mean) * inv * gv.w + bv.w;
    ((float4*)(out + row * C_))[threadIdx.x] = o;
}

// ---------------- QKV projection ----------------
__global__ __launch_bounds__(256, 2)
void qkv_kernel(const float* __restrict__ wq, const float* __restrict__ wk,
                const float* __restrict__ wv)
{
    int m0   = blockIdx.x * 128;
    int sel  = blockIdx.y >> 3;
    int head = blockIdx.y & 7;
    const float* W = (sel == 0 ? wq : sel == 1 ? wk : wv) + (size_t)head * C_ * DH_;
    float* O = (sel == 0 ? g_q : sel == 1 ? g_k : g_v);

    float acc[8][8] = {};
    gemm_core<false>(g_h1 + (size_t)m0 * C_, C_, W, DH_, C_, acc);

    int tx = threadIdx.x & 15, ty = threadIdx.x >> 4;
    #pragma unroll
    for (int i = 0; i < 8; i++) {
        int m = m0 + ty * 8 + i;
        int b = m >> 11, t = m & (T_ - 1);
        float* dst = O + ((size_t)(b * H_ + head) * T_ + t) * DH_ + tx * 8;
        *(float4*)(dst)     = make_float4(acc[i][0], acc[i][1], acc[i][2], acc[i][3]);
        *(float4*)(dst + 4) = make_float4(acc[i][4], acc[i][5], acc[i][6], acc[i][7]);
    }
}

// ---------------- scores = q k^T * sqrt(Dh) ----------------
__global__ __launch_bounds__(256, 2)
void scores_kernel()
{
    int z  = blockIdx.z;                         // b*H + h
    int m0 = blockIdx.x * 128, n0 = blockIdx.y * 128;
    const float* A = g_q + (size_t)z * T_ * DH_ + (size_t)m0 * DH_;
    const float* Bm = g_k + (size_t)z * T_ * DH_ + (size_t)n0 * DH_;

    float acc[8][8] = {};
    gemm_core<true>(A, DH_, Bm, DH_, DH_, acc);

    const float alpha = 11.313708498984761f;     // sqrt(128)
    int tx = threadIdx.x & 15, ty = threadIdx.x >> 4;
    float* out = g_sc + (size_t)z * T_ * T_ + (size_t)m0 * T_ + n0;
    #pragma unroll
    for (int i = 0; i < 8; i++) {
        float* dst = out + (size_t)(ty * 8 + i) * T_ + tx * 8;
        *(float4*)(dst)     = make_float4(acc[i][0]*alpha, acc[i][1]*alpha, acc[i][2]*alpha, acc[i][3]*alpha);
        *(float4*)(dst + 4) = make_float4(acc[i][4]*alpha, acc[i][5]*alpha, acc[i][6]*alpha, acc[i][7]*alpha);
    }
}

// ---------------- row softmax over 2048 ----------------
__global__ void softmax_kernel()
{
    size_t row = blockIdx.x;
    float* p = g_sc + row * T_;
    float4 v0 = *(float4*)(p + threadIdx.x * 8);
    float4 v1 = *(float4*)(p + threadIdx.x * 8 + 4);

    float mx = fmaxf(fmaxf(fmaxf(v0.x, v0.y), fmaxf(v0.z, v0.w)),
                     fmaxf(fmaxf(v1.x, v1.y), fmaxf(v1.z, v1.w)));
    #pragma unroll
    for (int o = 16; o; o >>= 1) mx = fmaxf(mx, __shfl_xor_sync(0xFFFFFFFFu, mx, o));
    __shared__ float sm[8];
    int w = threadIdx.x >> 5, l = threadIdx.x & 31;
    if (l == 0) sm[w] = mx;
    __syncthreads();
    mx = fmaxf(fmaxf(fmaxf(sm[0], sm[1]), fmaxf(sm[2], sm[3])),
               fmaxf(fmaxf(sm[4], sm[5]), fmaxf(sm[6], sm[7])));

    v0.x = expf(v0.x - mx); v0.y = expf(v0.y - mx); v0.z = expf(v0.z - mx); v0.w = expf(v0.w - mx);
    v1.x = expf(v1.x - mx); v1.y = expf(v1.y - mx); v1.z = expf(v1.z - mx); v1.w = expf(v1.w - mx);
    float s = v0.x + v0.y + v0.z + v0.w + v1.x + v1.y + v1.z + v1.w;
    float s2 = s;
    __syncthreads();   // reuse sm[]
    block_reduce2(s, s2);
    float inv = 1.0f / s;
    v0.x *= inv; v0.y *= inv; v0.z *= inv; v0.w *= inv;
    v1.x *= inv; v1.y *= inv; v1.z *= inv; v1.w *= inv;
    *(float4*)(p + threadIdx.x * 8)     = v0;
    *(float4*)(p + threadIdx.x * 8 + 4) = v1;
}

// ---------------- o = P @ V ; x1 = x + concat(o) ----------------
__global__ __launch_bounds__(256, 2)
void o_kernel(const float* __restrict__ x)
{
    int z = blockIdx.z;
    int b = z >> 3, head = z & 7;
    int m0 = blockIdx.x * 128;
    const float* A  = g_sc + (size_t)z * T_ * T_ + (size_t)m0 * T_;
    const float* Bm = g_v  + (size_t)z * T_ * DH_;

    float acc[8][8] = {};
    gemm_core<false>(A, T_, Bm, DH_, T_, acc);

    int tx = threadIdx.x & 15, ty = threadIdx.x >> 4;
    #pragma unroll
    for (int i = 0; i < 8; i++) {
        int t = m0 + ty * 8 + i;
        size_t idx = ((size_t)(b * T_ + t)) * C_ + head * DH_ + tx * 8;
        float4 r0 = *(const float4*)(x + idx);
        float4 r1 = *(const float4*)(x + idx + 4);
        *(float4*)(g_x1 + idx)     = make_float4(acc[i][0]+r0.x, acc[i][1]+r0.y, acc[i][2]+r0.z, acc[i][3]+r0.w);
        *(float4*)(g_x1 + idx + 4) = make_float4(acc[i][4]+r1.x, acc[i][5]+r1.y, acc[i][6]+r1.z, acc[i][7]+r1.w);
    }
}

// ---------------- ff1 = relu(h2 @ w1 + b1) ----------------
__global__ __launch_bounds__(256, 2)
void ff1_kernel(const float* __restrict__ w1, const float* __restrict__ b1)
{
    int m0 = blockIdx.x * 128, n0 = blockIdx.y * 128;
    float acc[8][8] = {};
    gemm_core<false>(g_h2 + (size_t)m0 * C_, C_, w1 + n0, DFF_, C_, acc);

    int tx = threadIdx.x & 15, ty = threadIdx.x >> 4;
    float4 bv0 = *(const float4*)(b1 + n0 + tx * 8);
    float4 bv1 = *(const float4*)(b1 + n0 + tx * 8 + 4);
    #pragma unroll
    for (int i = 0; i < 8; i++) {
        float* dst = g_f1 + (size_t)(m0 + ty * 8 + i) * DFF_ + n0 + tx * 8;
        *(float4*)(dst) = make_float4(fmaxf(acc[i][0]+bv0.x, 0.f), fmaxf(acc[i][1]+bv0.y, 0.f),
                                      fmaxf(acc[i][2]+bv0.z, 0.f), fmaxf(acc[i][3]+bv0.w, 0.f));
        *(float4*)(dst + 4) = make_float4(fmaxf(acc[i][4]+bv1.x, 0.f), fmaxf(acc[i][5]+bv1.y, 0.f),
                                          fmaxf(acc[i][6]+bv1.z, 0.f), fmaxf(acc[i][7]+bv1.w, 0.f));
    }
}

// ---------------- out = x1 + ff1 @ w2 + b2 ----------------
__global__ __launch_bounds__(256, 2)
void ff2_kernel(const float* __restrict__ w2, const float* __restrict__ b2,
                float* __restrict__ out)
{
    int m0 = blockIdx.x * 128, n0 = blockIdx.y * 128;
    float acc[8][8] = {};
    gemm_core<false>(g_f1 + (size_t)m0 * DFF_, DFF_, w2 + n0, C_, DFF_, acc);

    int tx = threadIdx.x & 15, ty = threadIdx.x >> 4;
    float4 bv0 = *(const float4*)(b2 + n0 + tx * 8);
    float4 bv1 = *(const float4*)(b2 + n0 + tx * 8 + 4);
    #pragma unroll
    for (int i = 0; i < 8; i++) {
        size_t idx = (size_t)(m0 + ty * 8 + i) * C_ + n0 + tx * 8;
        float4 r0 = *(const float4*)(g_x1 + idx);
        float4 r1 = *(const float4*)(g_x1 + idx + 4);
        *(float4*)(out + idx)     = make_float4(acc[i][0]+bv0.x+r0.x, acc[i][1]+bv0.y+r0.y,
                                                acc[i][2]+bv0.z+r0.z, acc[i][3]+bv0.w+r0.w);
        *(float4*)(out + idx + 4) = make_float4(acc[i][4]+bv1.x+r1.x, acc[i][5]+bv1.y+r1.y,
                                                acc[i][6]+bv1.z+r1.z, acc[i][7]+bv1.w+r1.w);
    }
}

// ---------------- host ----------------
extern "C" void kernel_launch(void* const* d_in, const int* in_sizes, int n_in,
                              void* d_out, int out_size)
{
    const float* x     = (const float*)d_in[0];
    const float* wq    = (const float*)d_in[1];
    const float* wk    = (const float*)d_in[2];
    const float* wv    = (const float*)d_in[3];
    const float* w1    = (const float*)d_in[4];
    const float* b1    = (const float*)d_in[5];
    const float* w2    = (const float*)d_in[6];
    const float* b2    = (const float*)d_in[7];
    const float* ln1_g = (const float*)d_in[8];
    const float* ln1_b = (const float*)d_in[9];
    const float* ln2_g = (const float*)d_in[10];
    const float* ln2_b = (const float*)d_in[11];
    float* out = (float*)d_out;

    float *p_h1, *p_x1, *p_h2;
    cudaGetSymbolAddress((void**)&p_h1, g_h1);
    cudaGetSymbolAddress((void**)&p_x1, g_x1);
    cudaGetSymbolAddress((void**)&p_h2, g_h2);

    // 1. LN1
    ln_kernel<<<M_, 256>>>(x, ln1_g, ln1_b, p_h1);
    // 2. QKV
    qkv_kernel<<<dim3(M_ / 128, 3 * H_, 1), 256>>>(wq, wk, wv);
    // 3. scores
    scores_kernel<<<dim3(T_ / 128, T_ / 128, B_ * H_), 256>>>();
    // 4. softmax
    softmax_kernel<<<B_ * H_ * T_, 256>>>();
    // 5. attention out + residual
    o_kernel<<<dim3(T_ / 128, 1, B_ * H_), 256>>>(x);
    // 6. LN2
    ln_kernel<<<M_, 256>>>(p_x1, ln2_g, ln2_b, p_h2);
    // 7. FF1
    ff1_kernel<<<dim3(M_ / 128, DFF_ / 128, 1), 256>>>(w1, b1);
    // 8. FF2 (+bias +residual) -> out
    ff2_kernel<<<dim3(M_ / 128, C_ / 128, 1), 256>>>(w2, b2, out);
}

// round 5
// speedup vs baseline: 1.7600x; 1.7600x over previous
#include <cuda_runtime.h>
#include <cuda_bf16.h>
#include <cstdint>
#include <math.h>

// ---------------- problem constants ----------------
#define B_  4
#define T_  2048
#define C_  1024
#define H_  8
#define DH_ 128
#define DFF_ 4096
#define M_  (B_ * T_)            // 8192 rows

typedef __nv_bfloat16 bf16;

// ---------------- scratch (device globals, no allocation) ----------------
#define QKV_SZ (B_ * H_ * T_ * DH_)
__device__ bf16  g_h1h[M_ * C_],  g_h1l[M_ * C_];             // LN1 out hi/lo
__device__ bf16  g_q_h[QKV_SZ], g_q_l[QKV_SZ];
__device__ bf16  g_k_h[QKV_SZ], g_k_l[QKV_SZ];
__device__ float g_v  [QKV_SZ];
__device__ bf16  g_vT_h[QKV_SZ], g_vT_l[QKV_SZ];              // [z][Dh][T]
__device__ float g_sc[(size_t)B_ * H_ * T_ * T_];             // scores fp32
__device__ bf16  g_p_h[(size_t)B_ * H_ * T_ * T_];            // probs hi
__device__ bf16  g_p_l[(size_t)B_ * H_ * T_ * T_];            // probs lo
__device__ float g_x1[M_ * C_];                               // x + attn_out
__device__ bf16  g_h2h[M_ * C_], g_h2l[M_ * C_];              // LN2 out hi/lo
__device__ bf16  g_f1h[M_ * DFF_], g_f1l[M_ * DFF_];          // relu(h2 w1 + b1)
__device__ bf16  g_wTh[3 * H_ * DH_ * C_], g_wTl[3 * H_ * DH_ * C_];  // qkv w^T
__device__ bf16  g_w1Th[DFF_ * C_], g_w1Tl[DFF_ * C_];        // w1^T [Dff, C]
__device__ bf16  g_w2Th[C_ * DFF_], g_w2Tl[C_ * DFF_];        // w2^T [C, Dff]

// ---------------- low-level helpers ----------------
__device__ __forceinline__ uint32_t smem_u32(const void* p) {
    uint32_t a;
    asm("{ .reg .u64 t; cvta.to.shared.u64 t, %1; cvt.u32.u64 %0, t; }"
        : "=r"(a) : "l"(p));
    return a;
}
__device__ __forceinline__ void cp16(uint32_t dst, const void* src) {
    asm volatile("cp.async.cg.shared.global [%0], [%1], 16;\n"
                 :: "r"(dst), "l"(__cvta_generic_to_global(src)));
}
__device__ __forceinline__ void cp_commit() {
    asm volatile("cp.async.commit_group;\n" ::: "memory");
}
template<int N> __device__ __forceinline__ void cp_wait() {
    asm volatile("cp.async.wait_group %0;\n" :: "n"(N) : "memory");
}
__device__ __forceinline__ void ldsm4(uint32_t r[4], uint32_t addr) {
    asm volatile("ldmatrix.sync.aligned.m8n8.x4.shared.b16 {%0,%1,%2,%3}, [%4];"
        : "=r"(r[0]), "=r"(r[1]), "=r"(r[2]), "=r"(r[3]) : "r"(addr));
}
__device__ __forceinline__ void ldsm2(uint32_t r[2], uint32_t addr) {
    asm volatile("ldmatrix.sync.aligned.m8n8.x2.shared.b16 {%0,%1}, [%2];"
        : "=r"(r[0]), "=r"(r[1]) : "r"(addr));
}
__device__ __forceinline__ void mma_bf16(float c[4], const uint32_t a[4],
                                         const uint32_t b[2]) {
    asm volatile(
        "mma.sync.aligned.m16n8k16.row.col.f32.bf16.bf16.f32 "
        "{%0,%1,%2,%3}, {%4,%5,%6,%7}, {%8,%9}, {%0,%1,%2,%3};"
        : "+f"(c[0]), "+f"(c[1]), "+f"(c[2]), "+f"(c[3])
        : "r"(a[0]), "r"(a[1]), "r"(a[2]), "r"(a[3]), "r"(b[0]), "r"(b[1]));
}

// ---------------- smem geometry ----------------
// 4 mats per stage (Ah, Al, Bh, Bl), each 128 rows x 32 bf16, row stride 80B
// (80B = 20-bank stride -> ldmatrix 8-row groups hit 8 distinct 4-bank sets).
#define ROWB   80
#define MATB   (128 * ROWB)        // 10240
#define STAGEB (4 * MATB)          // 40960
#define GEMM_SMEM (2 * STAGEB)     // 81920

// ---------------- stage loader: gmem -> smem via cp.async ----------------
__device__ __forceinline__ void issue_stage(
    uint32_t sbase, int buf,
    const bf16* __restrict__ Ah, const bf16* __restrict__ Al, int lda,
    const bf16* __restrict__ Bh, const bf16* __restrict__ Bl, int ldb, int k0)
{
    const int tid = threadIdx.x;
    const int mat = tid >> 6;
    const int t   = tid & 63;
    const bf16* src; int ld;
    if      (mat == 0) { src = Ah; ld = lda; }
    else if (mat == 1) { src = Al; ld = lda; }
    else if (mat == 2) { src = Bh; ld = ldb; }
    else               { src = Bl; ld = ldb; }
    uint32_t mbase = sbase + (uint32_t)buf * STAGEB + (uint32_t)mat * MATB;
    #pragma unroll
    for (int rr = 0; rr < 2; rr++) {
        int row = t * 2 + rr;
        const bf16* s = src + (size_t)row * ld + k0;
        uint32_t d = mbase + row * ROWB;
        #pragma unroll
        for (int seg = 0; seg < 4; seg++)
            cp16(d + seg * 16, s + seg * 8);
    }
    cp_commit();
}

// ---------------- block GEMM mainloop ----------------
// D(128x128 fp32) = (Ah+Al)(128xK) * (Bh+Bl)(128xK)^T, 3-term bf16 split.
// acc[mi][ni][4] per thread; warp (wid&3)->M32, (wid>>2)->N64.
__device__ __forceinline__ void gemm_mainloop(
    float acc[2][8][4],
    const bf16* __restrict__ Ah, const bf16* __restrict__ Al, int lda,
    const bf16* __restrict__ Bh, const bf16* __restrict__ Bl, int ldb, int K)
{
    extern __shared__ char smem_raw[];
    uint32_t sbase = smem_u32(smem_raw);
    const int tid  = threadIdx.x;
    const int wid  = tid >> 5, lane = tid & 31;
    const int m0w  = (wid & 3) * 32;
    const int n0w  = (wid >> 2) * 64;
    const int g    = lane >> 3, lr = lane & 7;

    // ldmatrix per-lane byte offsets within a mat
    const uint32_t a_off = (uint32_t)((m0w + (g & 1) * 8 + lr) * ROWB + (g >> 1) * 16);
    const uint32_t b_off = (uint32_t)((n0w + lr) * ROWB + (g & 1) * 16);

    #pragma unroll
    for (int mi = 0; mi < 2; mi++)
        #pragma unroll
        for (int ni = 0; ni < 8; ni++)
            #pragma unroll
            for (int i = 0; i < 4; i++)
                acc[mi][ni][i] = 0.f;

    const int nstage = K >> 5;
    issue_stage(sbase, 0, Ah, Al, lda, Bh, Bl, ldb, 0);

    for (int c = 0; c < nstage; c++) {
        if (c + 1 < nstage) {
            issue_stage(sbase, (c + 1) & 1, Ah, Al, lda, Bh, Bl, ldb, (c + 1) << 5);
            cp_wait<1>();
        } else {
            cp_wait<0>();
        }
        __syncthreads();

        uint32_t st = sbase + (uint32_t)(c & 1) * STAGEB;
        #pragma unroll
        for (int ks = 0; ks < 2; ks++) {
            uint32_t kb = (uint32_t)ks * 32;        // k16 step = 32 bytes
            uint32_t ah[2][4], al[2][4];
            ldsm4(ah[0], st + 0 * MATB + a_off + kb);
            ldsm4(ah[1], st + 0 * MATB + a_off + kb + 16 * ROWB);
            ldsm4(al[0], st + 1 * MATB + a_off + kb);
            ldsm4(al[1], st + 1 * MATB + a_off + kb + 16 * ROWB);
            #pragma unroll
            for (int ni = 0; ni < 8; ni++) {
                uint32_t bh[2], bl[2];
                ldsm2(bh, st + 2 * MATB + b_off + kb + (uint32_t)ni * 8 * ROWB);
                ldsm2(bl, st + 3 * MATB + b_off + kb + (uint32_t)ni * 8 * ROWB);
                #pragma unroll
                for (int mi = 0; mi < 2; mi++) {
                    mma_bf16(acc[mi][ni], ah[mi], bh);
                    mma_bf16(acc[mi][ni], ah[mi], bl);
                    mma_bf16(acc[mi][ni], al[mi], bh);
                }
            }
        }
        __syncthreads();
    }
}

// epilogue iteration: calls f(ml, nl, float2) for this thread's 32 output pairs
template<class F>
__device__ __forceinline__ void epilogue_loop(float acc[2][8][4], F f)
{
    const int wid = threadIdx.x >> 5, lane = threadIdx.x & 31;
    const int m0w = (wid & 3) * 32, n0w = (wid >> 2) * 64;
    const int lr = lane >> 2, lc = (lane & 3) * 2;
    #pragma unroll
    for (int mi = 0; mi < 2; mi++)
        #pragma unroll
        for (int hf = 0; hf < 2; hf++) {
            const int ml = m0w + mi * 16 + hf * 8 + lr;
            #pragma unroll
            for (int ni = 0; ni < 8; ni++) {
                const int nl = n0w + ni * 8 + lc;
                f(ml, nl, make_float2(acc[mi][ni][hf * 2], acc[mi][ni][hf * 2 + 1]));
            }
        }
}

__device__ __forceinline__ void store_hilo2(bf16* oh, bf16* ol, float2 v) {
    bf16 h0 = __float2bfloat16_rn(v.x);
    bf16 h1 = __float2bfloat16_rn(v.y);
    __nv_bfloat162 hh; hh.x = h0; hh.y = h1;
    __nv_bfloat162 ll;
    ll.x = __float2bfloat16_rn(v.x - __bfloat162float(h0));
    ll.y = __float2bfloat16_rn(v.y - __bfloat162float(h1));
    *reinterpret_cast<__nv_bfloat162*>(oh) = hh;
    *reinterpret_cast<__nv_bfloat162*>(ol) = ll;
}

// ============================================================================
// GEMM kernels
// ============================================================================
__global__ void __launch_bounds__(256) qkv_gemm()
{
    int m0   = blockIdx.x * 128;
    int sel  = blockIdx.y >> 3;
    int head = blockIdx.y & 7;
    size_t woff = (size_t)blockIdx.y * DH_ * C_;
    float acc[2][8][4];
    gemm_mainloop(acc,
        g_h1h + (size_t)m0 * C_, g_h1l + (size_t)m0 * C_, C_,
        g_wTh + woff,            g_wTl + woff,            C_, C_);

    epilogue_loop(acc, [&](int ml, int nl, float2 vv) {
        int m = m0 + ml, b = m >> 11, t = m & (T_ - 1);
        size_t base = ((size_t)(b * H_ + head) * T_ + t) * DH_ + nl;
        if (sel == 0)      store_hilo2(g_q_h + base, g_q_l + base, vv);
        else if (sel == 1) store_hilo2(g_k_h + base, g_k_l + base, vv);
        else               *(float2*)(g_v + base) = vv;
    });
}

__global__ void __launch_bounds__(256) qk_gemm()
{
    int z = blockIdx.z, m0 = blockIdx.x * 128, n0 = blockIdx.y * 128;
    size_t zb = (size_t)z * T_ * DH_;
    float acc[2][8][4];
    gemm_mainloop(acc,
        g_q_h + zb + (size_t)m0 * DH_, g_q_l + zb + (size_t)m0 * DH_, DH_,
        g_k_h + zb + (size_t)n0 * DH_, g_k_l + zb + (size_t)n0 * DH_, DH_, DH_);

    const float AL = 11.313708498984761f;   // sqrt(128)
    float* outp = g_sc + (size_t)z * T_ * T_;
    epilogue_loop(acc, [&](int ml, int nl, float2 vv) {
        *(float2*)(outp + (size_t)(m0 + ml) * T_ + n0 + nl) =
            make_float2(vv.x * AL, vv.y * AL);
    });
}

__global__ void __launch_bounds__(256) pv_gemm(const float* __restrict__ x)
{
    int z = blockIdx.z, m0 = blockIdx.x * 128;
    int b = z >> 3, head = z & 7;
    size_t pb = (size_t)z * T_ * T_ + (size_t)m0 * T_;
    size_t vb = (size_t)z * DH_ * T_;
    float acc[2][8][4];
    gemm_mainloop(acc,
        g_p_h + pb, g_p_l + pb, T_,
        g_vT_h + vb, g_vT_l + vb, T_, T_);

    epilogue_loop(acc, [&](int ml, int nl, float2 vv) {
        int t = m0 + ml;
        size_t idx = ((size_t)(b * T_ + t)) * C_ + head * DH_ + nl;
        float2 xr = *(const float2*)(x + idx);
        *(float2*)(g_x1 + idx) = make_float2(vv.x + xr.x, vv.y + xr.y);
    });
}

__global__ void __launch_bounds__(256) ff1_gemm(const float* __restrict__ b1)
{
    int m0 = blockIdx.x * 128, n0 = blockIdx.y * 128;
    float acc[2][8][4];
    gemm_mainloop(acc,
        g_h2h + (size_t)m0 * C_,  g_h2l + (size_t)m0 * C_,  C_,
        g_w1Th + (size_t)n0 * C_, g_w1Tl + (size_t)n0 * C_, C_, C_);

    epilogue_loop(acc, [&](int ml, int nl, float2 vv) {
        float2 bb = *(const float2*)(b1 + n0 + nl);
        float r0 = fmaxf(vv.x + bb.x, 0.f);
        float r1 = fmaxf(vv.y + bb.y, 0.f);
        size_t base = (size_t)(m0 + ml) * DFF_ + n0 + nl;
        store_hilo2(g_f1h + base, g_f1l + base, make_float2(r0, r1));
    });
}

__global__ void __launch_bounds__(256) ff2_gemm(const float* __restrict__ b2,
                                                float* __restrict__ out)
{
    int m0 = blockIdx.x * 128, n0 = blockIdx.y * 128;
    float acc[2][8][4];
    gemm_mainloop(acc,
        g_f1h + (size_t)m0 * DFF_,  g_f1l + (size_t)m0 * DFF_,  DFF_,
        g_w2Th + (size_t)n0 * DFF_, g_w2Tl + (size_t)n0 * DFF_, DFF_, DFF_);

    epilogue_loop(acc, [&](int ml, int nl, float2 vv) {
        float2 bb = *(const float2*)(b2 + n0 + nl);
        size_t idx = (size_t)(m0 + ml) * C_ + n0 + nl;
        float2 xr = *(const float2*)(g_x1 + idx);
        *(float2*)(out + idx) = make_float2(vv.x + bb.x + xr.x,
                                            vv.y + bb.y + xr.y);
    });
}

// ============================================================================
// transpose + bf16 hi/lo convert: in [R, Cc] fp32 -> out [Cc, R] hi/lo
// ============================================================================
__global__ void transpose_conv(const float* __restrict__ in, bf16* __restrict__ oh,
                               bf16* __restrict__ ol, int R, int Cc,
                               size_t in_bstride, size_t out_bstride)
{
    __shared__ float tile[32][33];
    const float* src = in + (size_t)blockIdx.z * in_bstride;
    int c0 = blockIdx.x * 32, r0 = blockIdx.y * 32;
    int tx = threadIdx.x, ty = threadIdx.y;          // 32 x 8
    #pragma unroll
    for (int i = 0; i < 32; i += 8)
        tile[ty + i][tx] = src[(size_t)(r0 + ty + i) * Cc + c0 + tx];
    __syncthreads();
    #pragma unroll
    for (int i = 0; i < 32; i += 8) {
        float v = tile[tx][ty + i];
        bf16 h = __float2bfloat16_rn(v);
        bf16 l = __float2bfloat16_rn(v - __bfloat162float(h));
        size_t o = (size_t)blockIdx.z * out_bstride + (size_t)(c0 + ty + i) * R + r0 + tx;
        oh[o] = h; ol[o] = l;
    }
}

// ============================================================================
// LayerNorm -> bf16 hi/lo
// ============================================================================
__device__ __forceinline__ void block_reduce2(float& a, float& b)
{
    #pragma unroll
    for (int o = 16; o; o >>= 1) {
        a += __shfl_xor_sync(0xFFFFFFFFu, a, o);
        b += __shfl_xor_sync(0xFFFFFFFFu, b, o);
    }
    __shared__ float sa[8], sb_[8];
    int w = threadIdx.x >> 5, l = threadIdx.x & 31;
    if (l == 0) { sa[w] = a; sb_[w] = b; }
    __syncthreads();
    a = 0.f; b = 0.f;
    #pragma unroll
    for (int i = 0; i < 8; i++) { a += sa[i]; b += sb_[i]; }
}

__global__ void ln_kernel(const float* __restrict__ x, const float* __restrict__ g,
                          const float* __restrict__ bb, bf16* __restrict__ oh,
                          bf16* __restrict__ ol)
{
    size_t row = blockIdx.x;
    float4 v = ((const float4*)(x + row * C_))[threadIdx.x];
    float s  = v.x + v.y + v.z + v.w;
    float sq = v.x*v.x + v.y*v.y + v.z*v.z + v.w*v.w;
    block_reduce2(s, sq);
    float mean = s * (1.0f / C_);
    float var  = sq * (1.0f / C_) - mean * mean;
    float inv  = rsqrtf(var + 1e-5f);
    float4 gv = ((const float4*)g)[threadIdx.x];
    float4 bv = ((const float4*)bb)[threadIdx.x];
    float o0 = (v.x - mean) * inv * gv.x + bv.x;
    float o1 = (v.y - mean) * inv * gv.y + bv.y;
    float o2 = (v.z - mean) * inv * gv.z + bv.z;
    float o3 = (v.w - mean) * inv * gv.w + bv.w;
    size_t base = row * C_ + threadIdx.x * 4;
    store_hilo2(oh + base,     ol + base,     make_float2(o0, o1));
    store_hilo2(oh + base + 2, ol + base + 2, make_float2(o2, o3));
}

// ============================================================================
// row softmax over 2048, fp32 scores in -> bf16 hi/lo probs out
// ============================================================================
__global__ void softmax_kernel()
{
    size_t row = blockIdx.x;
    const float* p = g_sc + row * T_;
    float4 v0 = *(const float4*)(p + threadIdx.x * 8);
    float4 v1 = *(const float4*)(p + threadIdx.x * 8 + 4);

    float mx = fmaxf(fmaxf(fmaxf(v0.x, v0.y), fmaxf(v0.z, v0.w)),
                     fmaxf(fmaxf(v1.x, v1.y), fmaxf(v1.z, v1.w)));
    #pragma unroll
    for (int o = 16; o; o >>= 1) mx = fmaxf(mx, __shfl_xor_sync(0xFFFFFFFFu, mx, o));
    __shared__ float sm[8];
    int w = threadIdx.x >> 5, l = threadIdx.x & 31;
    if (l == 0) sm[w] = mx;
    __syncthreads();
    mx = fmaxf(fmaxf(fmaxf(sm[0], sm[1]), fmaxf(sm[2], sm[3])),
               fmaxf(fmaxf(sm[4], sm[5]), fmaxf(sm[6], sm[7])));

    v0.x = expf(v0.x - mx); v0.y = expf(v0.y - mx); v0.z = expf(v0.z - mx); v0.w = expf(v0.w - mx);
    v1.x = expf(v1.x - mx); v1.y = expf(v1.y - mx); v1.z = expf(v1.z - mx); v1.w = expf(v1.w - mx);
    float s = v0.x + v0.y + v0.z + v0.w + v1.x + v1.y + v1.z + v1.w;
    float s2 = s;
    __syncthreads();
    block_reduce2(s, s2);
    float inv = 1.0f / s;
    float vals[8] = {v0.x*inv, v0.y*inv, v0.z*inv, v0.w*inv,
                     v1.x*inv, v1.y*inv, v1.z*inv, v1.w*inv};
    size_t base = row * T_ + threadIdx.x * 8;
    #pragma unroll
    for (int j = 0; j < 8; j += 2)
        store_hilo2(g_p_h + base + j, g_p_l + base + j,
                    make_float2(vals[j], vals[j + 1]));
}

// ============================================================================
// host
// ============================================================================
extern "C" void kernel_launch(void* const* d_in, const int* in_sizes, int n_in,
                              void* d_out, int out_size)
{
    const float* x     = (const float*)d_in[0];
    const float* wq    = (const float*)d_in[1];
    const float* wk    = (const float*)d_in[2];
    const float* wv    = (const float*)d_in[3];
    const float* w1    = (const float*)d_in[4];
    const float* b1    = (const float*)d_in[5];
    const float* w2    = (const float*)d_in[6];
    const float* b2    = (const float*)d_in[7];
    const float* ln1_g = (const float*)d_in[8];
    const float* ln1_b = (const float*)d_in[9];
    const float* ln2_g = (const float*)d_in[10];
    const float* ln2_b = (const float*)d_in[11];
    float* out = (float*)d_out;

    cudaFuncSetAttribute(qkv_gemm, cudaFuncAttributeMaxDynamicSharedMemorySize, GEMM_SMEM);
    cudaFuncSetAttribute(qk_gemm,  cudaFuncAttributeMaxDynamicSharedMemorySize, GEMM_SMEM);
    cudaFuncSetAttribute(pv_gemm,  cudaFuncAttributeMaxDynamicSharedMemorySize, GEMM_SMEM);
    cudaFuncSetAttribute(ff1_gemm, cudaFuncAttributeMaxDynamicSharedMemorySize, GEMM_SMEM);
    cudaFuncSetAttribute(ff2_gemm, cudaFuncAttributeMaxDynamicSharedMemorySize, GEMM_SMEM);

    bf16 *p_h1h, *p_h1l, *p_h2h, *p_h2l, *p_wTh, *p_wTl, *p_w1Th, *p_w1Tl, *p_w2Th, *p_w2Tl;
    bf16 *p_vTh, *p_vTl;
    float *p_x1, *p_v;
    cudaGetSymbolAddress((void**)&p_h1h, g_h1h);
    cudaGetSymbolAddress((void**)&p_h1l, g_h1l);
    cudaGetSymbolAddress((void**)&p_h2h, g_h2h);
    cudaGetSymbolAddress((void**)&p_h2l, g_h2l);
    cudaGetSymbolAddress((void**)&p_wTh, g_wTh);
    cudaGetSymbolAddress((void**)&p_wTl, g_wTl);
    cudaGetSymbolAddress((void**)&p_w1Th, g_w1Th);
    cudaGetSymbolAddress((void**)&p_w1Tl, g_w1Tl);
    cudaGetSymbolAddress((void**)&p_w2Th, g_w2Th);
    cudaGetSymbolAddress((void**)&p_w2Tl, g_w2Tl);
    cudaGetSymbolAddress((void**)&p_vTh, g_vT_h);
    cudaGetSymbolAddress((void**)&p_vTl, g_vT_l);
    cudaGetSymbolAddress((void**)&p_x1, g_x1);
    cudaGetSymbolAddress((void**)&p_v,  g_v);

    dim3 tb(32, 8);
    // weight transposes -> [N, K] bf16 hi/lo
    transpose_conv<<<dim3(DH_/32, C_/32, H_), tb>>>(wq, p_wTh, p_wTl, C_, DH_, (size_t)C_*DH_, (size_t)DH_*C_);
    transpose_conv<<<dim3(DH_/32, C_/32, H_), tb>>>(wk, p_wTh + (size_t)H_*DH_*C_, p_wTl + (size_t)H_*DH_*C_, C_, DH_, (size_t)C_*DH_, (size_t)DH_*C_);
    transpose_conv<<<dim3(DH_/32, C_/32, H_), tb>>>(wv, p_wTh + (size_t)2*H_*DH_*C_, p_wTl + (size_t)2*H_*DH_*C_, C_, DH_, (size_t)C_*DH_, (size_t)DH_*C_);
    transpose_conv<<<dim3(DFF_/32, C_/32, 1), tb>>>(w1, p_w1Th, p_w1Tl, C_, DFF_, 0, 0);
    transpose_conv<<<dim3(C_/32, DFF_/32, 1), tb>>>(w2, p_w2Th, p_w2Tl, DFF_, C_, 0, 0);

    // 1. LN1 -> h1 hi/lo
    ln_kernel<<<M_, 256>>>(x, ln1_g, ln1_b, p_h1h, p_h1l);
    // 2. QKV projections
    qkv_gemm<<<dim3(M_/128, 3*H_, 1), 256, GEMM_SMEM>>>();
    // 3. v transpose -> [z][Dh][T] hi/lo
    transpose_conv<<<dim3(DH_/32, T_/32, B_*H_), tb>>>(p_v, p_vTh, p_vTl, T_, DH_, (size_t)T_*DH_, (size_t)DH_*T_);
    // 4. scores
    qk_gemm<<<dim3(T_/128, T_/128, B_*H_), 256, GEMM_SMEM>>>();
    // 5. softmax -> probs hi/lo
    softmax_kernel<<<B_*H_*T_, 256>>>();
    // 6. attention out + residual -> x1
    pv_gemm<<<dim3(T_/128, 1, B_*H_), 256, GEMM_SMEM>>>(x);
    // 7. LN2 -> h2 hi/lo
    ln_kernel<<<M_, 256>>>(p_x1, ln2_g, ln2_b, p_h2h, p_h2l);
    // 8. FF1 -> f1 hi/lo
    ff1_gemm<<<dim3(M_/128, DFF_/128, 1), 256, GEMM_SMEM>>>(b1);
    // 9. FF2 (+bias +residual) -> out
    ff2_gemm<<<dim3(M_/128, C_/128, 1), 256, GEMM_SMEM>>>(b2, out);
}